// round 3
// baseline (speedup 1.0000x reference)
#include <cuda_runtime.h>
#include <cuda_bf16.h>
#include <cstdint>
#include <cstddef>
#include <math.h>

#define NB   32      // batch
#define T1   2000    // layer-1 time steps
#define T2   1000    // layer-2 time steps (after pool s=2)
#define D1   80      // input feature dim
#define HH   256     // hidden per direction
#define G4H  1024    // 4*H gate rows
#define HDC  512     // 2*H (bidirectional concat)
#define OUTC 512     // final output channels

// ---------------- device scratch (static: allocation is forbidden) ----------
__device__ float g_xg1f[(size_t)T1 * G4H * NB];   // [t][gate_row][b]
__device__ float g_xg1b[(size_t)T1 * G4H * NB];
__device__ float g_xg2f[(size_t)T2 * G4H * NB];
__device__ float g_xg2b[(size_t)T2 * G4H * NB];
__device__ float g_out1[(size_t)NB * T1 * HDC];   // [b][t][ch]
__device__ float g_pool1[(size_t)NB * T2 * HDC];
__device__ float g_out2[(size_t)NB * T2 * HDC];
__device__ float g_hbuf[2 * 2 * HH * NB];         // [dir][parity][k][b]
__device__ unsigned g_barCnt;
__device__ volatile unsigned g_barGen;

// ---------------- small helpers ---------------------------------------------
__global__ void k_zero(float* __restrict__ p, size_t n) {
    size_t i = (size_t)blockIdx.x * blockDim.x + threadIdx.x;
    size_t st = (size_t)gridDim.x * blockDim.x;
    for (; i < n; i += st) p[i] = 0.f;
}

__global__ void k_init_rec() {
    for (int j = threadIdx.x; j < 2 * 2 * HH * NB; j += blockDim.x) g_hbuf[j] = 0.f;
    if (threadIdx.x == 0) { g_barCnt = 0u; g_barGen = 0u; }
}

__global__ void k_pool(const float* __restrict__ in, float* __restrict__ out) {
    size_t n = (size_t)NB * T2 * HDC;
    size_t i = (size_t)blockIdx.x * blockDim.x + threadIdx.x;
    size_t st = (size_t)gridDim.x * blockDim.x;
    for (; i < n; i += st) {
        int c  = (int)(i % HDC);
        size_t r = i / HDC;
        int tp = (int)(r % T2);
        int b  = (int)(r / T2);
        const float* p = in + ((size_t)b * T1 + 2 * (size_t)tp) * HDC + c;
        out[i] = fmaxf(p[0], p[HDC]);
    }
}

__global__ void k_lens(const int* __restrict__ xlen, float* __restrict__ out) {
    int i = threadIdx.x;
    if (i < NB) out[i] = (float)(xlen[i] >> 1);
}

// ---------------- tiled projection / linear GEMM ----------------------------
// out[t*ot + row*orr + b*ob] = bias[row] + sum_k W[row,k] * X[(b*Tt+t)*K + k]
// block: 64 rows x 32 batch, 128 threads, thread tile 4x4, K chunked by 32.
__global__ void __launch_bounds__(128) k_proj(
    const float* __restrict__ X, const float* __restrict__ W,
    const float* __restrict__ bias, float* __restrict__ out,
    int Tt, int K, long long ot, long long orr, long long ob)
{
    __shared__ float w_sh[32][68];   // [k][row], padded
    __shared__ float x_sh[32][36];   // [k][b],   padded
    const int t    = blockIdx.y;
    const int row0 = blockIdx.x * 64;
    const int tid  = threadIdx.x;
    const int rgp  = tid >> 3;   // 0..15 -> rows rgp*4 .. +3
    const int bgp  = tid & 7;    // 0..7  -> batch bgp*4 .. +3

    float acc[4][4] = {};

    for (int k0 = 0; k0 < K; k0 += 32) {
        const int kc = (K - k0 < 32) ? (K - k0) : 32;
        // stage W chunk 64 rows x 32 k (transposed)
        {
            const int r = tid >> 1, koff = (tid & 1) * 16;
            const float* wp = W + (size_t)(row0 + r) * K + k0 + koff;
#pragma unroll
            for (int j = 0; j < 16; j++) {
                int kk = koff + j;
                float v = 0.f;
                if (kk < kc) v = wp[j];
                w_sh[kk][r] = v;
            }
        }
        // stage X chunk 32 batch x 32 k (transposed)
        {
            const int b = tid >> 2, koff = (tid & 3) * 8;
            const float* xp = X + ((size_t)b * Tt + t) * K + k0 + koff;
#pragma unroll
            for (int j = 0; j < 8; j++) {
                int kk = koff + j;
                float v = 0.f;
                if (kk < kc) v = xp[j];
                x_sh[kk][b] = v;
            }
        }
        __syncthreads();
#pragma unroll 8
        for (int kk = 0; kk < 32; kk++) {
            float4 wv = *(const float4*)&w_sh[kk][rgp * 4];
            float4 xv = *(const float4*)&x_sh[kk][bgp * 4];
            acc[0][0] = fmaf(wv.x, xv.x, acc[0][0]);
            acc[0][1] = fmaf(wv.x, xv.y, acc[0][1]);
            acc[0][2] = fmaf(wv.x, xv.z, acc[0][2]);
            acc[0][3] = fmaf(wv.x, xv.w, acc[0][3]);
            acc[1][0] = fmaf(wv.y, xv.x, acc[1][0]);
            acc[1][1] = fmaf(wv.y, xv.y, acc[1][1]);
            acc[1][2] = fmaf(wv.y, xv.z, acc[1][2]);
            acc[1][3] = fmaf(wv.y, xv.w, acc[1][3]);
            acc[2][0] = fmaf(wv.z, xv.x, acc[2][0]);
            acc[2][1] = fmaf(wv.z, xv.y, acc[2][1]);
            acc[2][2] = fmaf(wv.z, xv.z, acc[2][2]);
            acc[2][3] = fmaf(wv.z, xv.w, acc[2][3]);
            acc[3][0] = fmaf(wv.w, xv.x, acc[3][0]);
            acc[3][1] = fmaf(wv.w, xv.y, acc[3][1]);
            acc[3][2] = fmaf(wv.w, xv.z, acc[3][2]);
            acc[3][3] = fmaf(wv.w, xv.w, acc[3][3]);
        }
        __syncthreads();
    }
#pragma unroll
    for (int i = 0; i < 4; i++) {
        const int row = row0 + rgp * 4 + i;
        const float bv = bias[row];
#pragma unroll
        for (int j = 0; j < 4; j++) {
            const int b = bgp * 4 + j;
            out[(size_t)t * ot + (size_t)row * orr + (size_t)b * ob] = acc[i][j] + bv;
        }
    }
}

// ---------------- persistent recurrent LSTM --------------------------------
// grid = 128 blocks: dir = blockIdx>>6, gb = blockIdx&63. Block owns h indices
// [gb*4, gb*4+4) for all 32 batches: 16 Whh rows (4 gates x 4 h) resident in
// shared. Each step: GEMM slice over full K=256 (K split across 4 warps, h
// read from L2 via __ldcg), cross-warp reduce in shared, pointwise LSTM update
// with (h,c) state in registers, grid barrier.
__device__ __forceinline__ float sigf(float x) {
    return 1.f / (1.f + __expf(-x));
}

__global__ void __launch_bounds__(128, 1) k_lstm(
    const float* __restrict__ xgF, const float* __restrict__ xgB,
    const float* __restrict__ WhhF, const float* __restrict__ WhhB,
    const int* __restrict__ xlen, int lenShift,
    float* __restrict__ out, int Tt)
{
    __shared__ float w_sh[HH * 16];     // [k][rr] rr = g*4+hj
    __shared__ float part[4 * 16 * NB]; // [warp][rr][b]

    const int dir = (int)(blockIdx.x >> 6);
    const int gb  = (int)(blockIdx.x & 63);
    const float* xg  = dir ? xgB : xgF;
    const float* Whh = dir ? WhhB : WhhF;
    float* hb = g_hbuf + dir * (2 * HH * NB);

    const int tid  = threadIdx.x;
    const int warp = tid >> 5, lane = tid & 31;
    const int bg = lane >> 2;     // batch group 0..7
    const int rg = lane & 3;      // row group 0..3
    const int kbase = warp * 64;  // K section per warp

    // one-time: stage Whh slice transposed: w_sh[k][rr] = Whh[(rr>>2)*256 + gb*4 + (rr&3)][k]
    {
        const int rr = tid & 15, kp = tid >> 4;    // kp 0..7
        const int grow = (rr >> 2) * HH + gb * 4 + (rr & 3);
        const float* wp = Whh + (size_t)grow * HH + kp * 32;
        float* ws = w_sh + rr;
#pragma unroll
        for (int j = 0; j < 32; j++) ws[(size_t)(kp * 32 + j) * 16] = wp[j];
    }

    // pointwise role: thread owns (hj = warp, b = lane)
    const int b_pt = lane;
    const int hj   = warp;
    const int hk   = gb * 4 + hj;
    const int len_b = xlen[b_pt] >> lenShift;
    float c_st = 0.f, h_st = 0.f;

    __syncthreads();

    for (int s = 0; s < Tt; s++) {
        const float* hrd = hb + (s & 1) * (HH * NB);
        float* hwr = hb + ((s & 1) ^ 1) * (HH * NB);

        // prefetch gate inputs (bwd gathers per-batch time-reversed)
        int tx = dir ? (len_b - 1 - s) : s;
        if (tx < 0) tx = 0;
        const float* xp = xg + (size_t)tx * (G4H * NB) + (size_t)hk * NB + b_pt;
        float xg0 = __ldg(xp);
        float xg1 = __ldg(xp + 256 * NB);
        float xg2 = __ldg(xp + 512 * NB);
        float xg3 = __ldg(xp + 768 * NB);

        // GEMM slice: acc[i][j] = sum_{k in section} Whh[row(rg*4+i)][k] * h[k][bg*4+j]
        float acc[4][4] = {};
        const float4* hp  = (const float4*)hrd + (size_t)kbase * 8 + bg;
        const float4* wp4 = (const float4*)w_sh + (size_t)kbase * 4 + rg;
#pragma unroll 8
        for (int k = 0; k < 64; k++) {
            float4 hv = __ldcg(hp + (size_t)k * 8);   // L2 (coherent) read of h
            float4 wv = wp4[(size_t)k * 4];
            acc[0][0] = fmaf(wv.x, hv.x, acc[0][0]);
            acc[0][1] = fmaf(wv.x, hv.y, acc[0][1]);
            acc[0][2] = fmaf(wv.x, hv.z, acc[0][2]);
            acc[0][3] = fmaf(wv.x, hv.w, acc[0][3]);
            acc[1][0] = fmaf(wv.y, hv.x, acc[1][0]);
            acc[1][1] = fmaf(wv.y, hv.y, acc[1][1]);
            acc[1][2] = fmaf(wv.y, hv.z, acc[1][2]);
            acc[1][3] = fmaf(wv.y, hv.w, acc[1][3]);
            acc[2][0] = fmaf(wv.z, hv.x, acc[2][0]);
            acc[2][1] = fmaf(wv.z, hv.y, acc[2][1]);
            acc[2][2] = fmaf(wv.z, hv.z, acc[2][2]);
            acc[2][3] = fmaf(wv.z, hv.w, acc[2][3]);
            acc[3][0] = fmaf(wv.w, hv.x, acc[3][0]);
            acc[3][1] = fmaf(wv.w, hv.y, acc[3][1]);
            acc[3][2] = fmaf(wv.w, hv.z, acc[3][2]);
            acc[3][3] = fmaf(wv.w, hv.w, acc[3][3]);
        }

        // cross-warp partials
        {
            float* pb = part + ((size_t)warp * 16 + rg * 4) * NB + bg * 4;
            *(float4*)(pb + 0 * NB) = make_float4(acc[0][0], acc[0][1], acc[0][2], acc[0][3]);
            *(float4*)(pb + 1 * NB) = make_float4(acc[1][0], acc[1][1], acc[1][2], acc[1][3]);
            *(float4*)(pb + 2 * NB) = make_float4(acc[2][0], acc[2][1], acc[2][2], acc[2][3]);
            *(float4*)(pb + 3 * NB) = make_float4(acc[3][0], acc[3][1], acc[3][2], acc[3][3]);
        }
        __syncthreads();

        // reduce + pointwise update for (hj, b_pt)
        float g0 = xg0, g1 = xg1, g2 = xg2, g3 = xg3;
#pragma unroll
        for (int w = 0; w < 4; w++) {
            const float* pr = part + (size_t)w * 16 * NB;
            g0 += pr[(0 + hj) * NB + b_pt];
            g1 += pr[(4 + hj) * NB + b_pt];
            g2 += pr[(8 + hj) * NB + b_pt];
            g3 += pr[(12 + hj) * NB + b_pt];
        }
        float ig = sigf(g0);
        float fg = sigf(g1);
        float gg = tanhf(g2);
        float og = sigf(g3);
        float c_n = fg * c_st + ig * gg;
        float h_n = og * tanhf(c_n);
        if (s < len_b) {
            c_st = c_n; h_st = h_n;
            int t_o = dir ? (len_b - 1 - s) : s;
            out[((size_t)b_pt * Tt + t_o) * HDC + dir * HH + hk] = h_n;
        }
        hwr[hk * NB + b_pt] = h_st;

        // grid barrier (sense-reversal, all 128 blocks co-resident)
        __threadfence();
        __syncthreads();
        if (tid == 0) {
            unsigned gen = g_barGen;
            if (atomicAdd(&g_barCnt, 1u) == 127u) {
                g_barCnt = 0u;
                __threadfence();
                g_barGen = gen + 1u;
            } else {
                while (g_barGen == gen) { }
            }
        }
        __syncthreads();
    }
}

// ---------------- host orchestration ----------------------------------------
extern "C" void kernel_launch(void* const* d_in, const int* in_sizes, int n_in,
                              void* d_out, int out_size) {
    const float* x     = (const float*)d_in[0];
    const int*   xlen  = (const int*)d_in[1];
    const float* Wih1f = (const float*)d_in[2];
    const float* Whh1f = (const float*)d_in[3];
    const float* b1f   = (const float*)d_in[4];
    const float* Wih1b = (const float*)d_in[5];
    const float* Whh1b = (const float*)d_in[6];
    const float* b1b   = (const float*)d_in[7];
    const float* Wih2f = (const float*)d_in[8];
    const float* Whh2f = (const float*)d_in[9];
    const float* b2f   = (const float*)d_in[10];
    const float* Wih2b = (const float*)d_in[11];
    const float* Whh2b = (const float*)d_in[12];
    const float* b2b   = (const float*)d_in[13];
    const float* Wlin  = (const float*)d_in[14];
    const float* blin  = (const float*)d_in[15];
    float* out = (float*)d_out;

    float *xg1f, *xg1b, *xg2f, *xg2b, *out1, *pool1, *out2;
    cudaGetSymbolAddress((void**)&xg1f,  g_xg1f);
    cudaGetSymbolAddress((void**)&xg1b,  g_xg1b);
    cudaGetSymbolAddress((void**)&xg2f,  g_xg2f);
    cudaGetSymbolAddress((void**)&xg2b,  g_xg2b);
    cudaGetSymbolAddress((void**)&out1,  g_out1);
    cudaGetSymbolAddress((void**)&pool1, g_pool1);
    cudaGetSymbolAddress((void**)&out2,  g_out2);

    const long long ot_xg = (long long)G4H * NB;   // xg layout [t][row][b]
    const long long or_xg = NB;
    const long long ob_xg = 1;

    // zero masked-output buffers (graph replays: must rewrite every call)
    k_zero<<<4096, 256>>>(out1, (size_t)NB * T1 * HDC);
    k_zero<<<4096, 256>>>(out2, (size_t)NB * T2 * HDC);

    // layer-1 gate projections (reversal commutes with the linear projection)
    k_proj<<<dim3(G4H / 64, T1), 128>>>(x, Wih1f, b1f, xg1f, T1, D1, ot_xg, or_xg, ob_xg);
    k_proj<<<dim3(G4H / 64, T1), 128>>>(x, Wih1b, b1b, xg1b, T1, D1, ot_xg, or_xg, ob_xg);

    // layer-1 recurrence (both directions, persistent)
    k_init_rec<<<1, 256>>>();
    k_lstm<<<128, 128>>>(xg1f, xg1b, Whh1f, Whh1b, xlen, 0, out1, T1);

    // max-pool stride 2
    k_pool<<<2048, 256>>>(out1, pool1);

    // layer-2 gate projections
    k_proj<<<dim3(G4H / 64, T2), 128>>>(pool1, Wih2f, b2f, xg2f, T2, HDC, ot_xg, or_xg, ob_xg);
    k_proj<<<dim3(G4H / 64, T2), 128>>>(pool1, Wih2b, b2b, xg2b, T2, HDC, ot_xg, or_xg, ob_xg);

    // layer-2 recurrence (lengths = x_len >> 1)
    k_init_rec<<<1, 256>>>();
    k_lstm<<<128, 128>>>(xg2f, xg2b, Whh2f, Whh2b, xlen, 1, out2, T2);

    // final linear: out[b][t][o] = out2[b][t][:] @ Wlin[o][:] + blin[o]
    k_proj<<<dim3(OUTC / 64, T2), 128>>>(out2, Wlin, blin, out, T2, HDC,
                                         (long long)OUTC, 1LL, (long long)T2 * OUTC);

    // lens = x_len // 2 appended as float (second tuple element)
    if (out_size > NB * T2 * OUTC) {
        k_lens<<<1, 32>>>(xlen, out + (size_t)NB * T2 * OUTC);
    }
}